// round 2
// baseline (speedup 1.0000x reference)
#include <cuda_runtime.h>
#include <cstdint>

#define B_SZ 2048
#define O_SZ 4096
#define I_SZ 4096
#define N_FFT 4096
#define LOG_N 12

// ---------------------------------------------------------------------------
// Scratch (device globals: no allocation allowed)
// ---------------------------------------------------------------------------
__device__ float2 g_Y [(size_t)O_SZ * I_SZ];   // after axis-1 IFFT, [p][i]
__device__ float2 g_Yt[(size_t)I_SZ * O_SZ];   // transposed,        [i][p]
__device__ float  g_Wt[(size_t)I_SZ * O_SZ];   // W^T (i-major),     [i][o]

__device__ __forceinline__ float2 cmul(float2 a, float2 b) {
    return make_float2(a.x * b.x - a.y * b.y, a.x * b.y + a.y * b.x);
}

// ---------------------------------------------------------------------------
// In-shared-memory 4096-point inverse FFT (sign +), input in bit-reversed
// order, output natural order, unnormalized. tw[j] = exp(+2*pi*i*j/4096),
// j in [0,1024); angles in [pi/2, pi) obtained by rotation by i.
// ---------------------------------------------------------------------------
__device__ __forceinline__ void ifft4096(float2* xs, const float2* tw) {
#pragma unroll
    for (int s = 1; s <= LOG_N; s++) {
        const int half = 1 << (s - 1);
        const int twsh = LOG_N - s;
        __syncthreads();
#pragma unroll
        for (int t = threadIdx.x; t < N_FFT / 2; t += 512) {
            int k  = t & (half - 1);
            int i0 = ((t >> (s - 1)) << s) + k;
            int i1 = i0 + half;
            int j  = k << twsh;           // in [0, 2048)
            float2 w;
            if (j < 1024) {
                w = tw[j];
            } else {
                float2 q = tw[j - 1024];
                w = make_float2(-q.y, q.x);
            }
            float2 u = xs[i0];
            float2 v = cmul(xs[i1], w);
            xs[i0] = make_float2(u.x + v.x, u.y + v.y);
            xs[i1] = make_float2(u.x - v.x, u.y - v.y);
        }
    }
    __syncthreads();
}

__device__ __forceinline__ void build_twiddles(float2* tw) {
    for (int j = threadIdx.x; j < 1024; j += 512) {
        float s, c;
        sincosf(1.5339807878856412e-3f * (float)j, &s, &c);  // 2*pi/4096 * j
        tw[j] = make_float2(c, s);
    }
}

// ---------------------------------------------------------------------------
// K1: per output-row p, build masked/zero-padded/doubled spectrum row and
// inverse-FFT it along axis 1. Writes g_Y[p][i] (coalesced).
// NOTE: zmat is int32 (JAX default x64-disabled downcasts the int64 arange).
// ---------------------------------------------------------------------------
__global__ __launch_bounds__(512) void kern_rowfft(const float* __restrict__ wr,
                                                   const float* __restrict__ wi,
                                                   const int* __restrict__ zmat) {
    __shared__ float2 xs[N_FFT];
    __shared__ float2 tw[1024];
    const int p = blockIdx.x;
    build_twiddles(tw);

    const size_t base = (size_t)p * I_SZ;
    for (int k = threadIdx.x; k < N_FFT; k += 512) {
        float2 v = make_float2(0.f, 0.f);
        if (k <= I_SZ / 2) {
            int z = zmat[base + k];
            if (z <= 8388608) {                       // KEEPRATE * O * I, exact
                float sc = (k == 0 || k == I_SZ / 2) ? 1.0f : 2.0f;
                v = make_float2(wr[base + k] * sc, wi[base + k] * sc);
            }
        }
        xs[__brev((unsigned)k) >> (32 - LOG_N)] = v;
    }
    ifft4096(xs, tw);

    float2* out = g_Y + base;
    for (int i = threadIdx.x; i < N_FFT; i += 512) out[i] = xs[i];
}

// ---------------------------------------------------------------------------
// K2: tiled transpose g_Y[p][i] -> g_Yt[i][p] (float2, 32x32 tiles)
// ---------------------------------------------------------------------------
__global__ void kern_transpose() {
    __shared__ float2 tile[32][33];
    int x = blockIdx.x * 32 + threadIdx.x;   // i
    int y = blockIdx.y * 32 + threadIdx.y;   // p
#pragma unroll
    for (int j = 0; j < 32; j += 8)
        tile[threadIdx.y + j][threadIdx.x] = g_Y[(size_t)(y + j) * I_SZ + x];
    __syncthreads();
    int x2 = blockIdx.y * 32 + threadIdx.x;  // p
    int y2 = blockIdx.x * 32 + threadIdx.y;  // i
#pragma unroll
    for (int j = 0; j < 32; j += 8)
        g_Yt[(size_t)(y2 + j) * O_SZ + x2] = tile[threadIdx.x][threadIdx.y + j];
}

// ---------------------------------------------------------------------------
// K3: per i, inverse-FFT along axis 0 (rows of g_Yt), keep Re * 1/(O*I).
// Writes g_Wt[i][o] (coalesced).
// ---------------------------------------------------------------------------
__global__ __launch_bounds__(512) void kern_colfft() {
    __shared__ float2 xs[N_FFT];
    __shared__ float2 tw[1024];
    const int i = blockIdx.x;
    build_twiddles(tw);

    const float2* row = g_Yt + (size_t)i * O_SZ;
    for (int p = threadIdx.x; p < N_FFT; p += 512)
        xs[__brev((unsigned)p) >> (32 - LOG_N)] = row[p];
    ifft4096(xs, tw);

    float* out = g_Wt + (size_t)i * O_SZ;
    const float scale = 1.0f / 16777216.0f;   // 1/(O*I)
    for (int o = threadIdx.x; o < N_FFT; o += 512) out[o] = xs[o].x * scale;
}

// ---------------------------------------------------------------------------
// K4: SGEMM (NN): C[b][o] = sum_i data[b][i] * Wt[i][o] + bias[o]
// 128x128 block tile, BK=16, 256 threads, 8x8 per thread, packed f32x2 FMA.
// ---------------------------------------------------------------------------
#define BM 128
#define BN 128
#define BK 16

__global__ __launch_bounds__(256) void kern_gemm(const float* __restrict__ A,
                                                 const float* __restrict__ bias,
                                                 float* __restrict__ C) {
    __shared__ float As[BK][BM];       // [k][m]
    __shared__ float Bs[BK][BN];       // [k][n]

    const int bn  = blockIdx.x;
    const int bm  = blockIdx.y;
    const int tid = threadIdx.x;
    const int tx  = tid & 15;          // n sub-tile
    const int ty  = tid >> 4;          // m sub-tile

    const float* Abase = A + (size_t)(bm * BM) * I_SZ;
    const float* Bbase = g_Wt + (size_t)(bn * BN);

    unsigned long long acc[8][4];
#pragma unroll
    for (int i = 0; i < 8; i++)
#pragma unroll
        for (int j = 0; j < 4; j++) acc[i][j] = 0ULL;

    for (int k0 = 0; k0 < I_SZ; k0 += BK) {
        // A tile: 128 rows x 16 k -> As[k][m] (transposed store)
#pragma unroll
        for (int r = 0; r < 2; r++) {
            int idx = tid + r * 256;        // 512 float4 total
            int row = idx >> 2;             // 0..127
            int c4  = idx & 3;              // 0..3
            float4 v = *(const float4*)(Abase + (size_t)row * I_SZ + k0 + c4 * 4);
            As[c4 * 4 + 0][row] = v.x;
            As[c4 * 4 + 1][row] = v.y;
            As[c4 * 4 + 2][row] = v.z;
            As[c4 * 4 + 3][row] = v.w;
        }
        // B tile: 16 rows x 128 n -> Bs[k][n] (natural, fully coalesced)
#pragma unroll
        for (int r = 0; r < 2; r++) {
            int idx = tid + r * 256;        // 512 float4 total
            int row = idx >> 5;             // 0..15
            int c4  = idx & 31;             // 0..31
            float4 v = *(const float4*)(Bbase + (size_t)(k0 + row) * O_SZ + c4 * 4);
            *(float4*)&Bs[row][c4 * 4] = v;
        }
        __syncthreads();

#pragma unroll
        for (int k = 0; k < BK; k++) {
            float a[8];
            *(float4*)&a[0] = *(const float4*)&As[k][ty * 8 + 0];
            *(float4*)&a[4] = *(const float4*)&As[k][ty * 8 + 4];

            union { float4 f4; unsigned long long u[2]; } b0, b1;
            b0.f4 = *(const float4*)&Bs[k][tx * 8 + 0];
            b1.f4 = *(const float4*)&Bs[k][tx * 8 + 4];
            unsigned long long bu[4] = { b0.u[0], b0.u[1], b1.u[0], b1.u[1] };

#pragma unroll
            for (int i = 0; i < 8; i++) {
                unsigned long long ad;
                asm("mov.b64 %0, {%1, %1};" : "=l"(ad) : "f"(a[i]));
#pragma unroll
                for (int j = 0; j < 4; j++) {
                    asm("fma.rn.f32x2 %0, %1, %2, %0;"
                        : "+l"(acc[i][j]) : "l"(ad), "l"(bu[j]));
                }
            }
        }
        __syncthreads();
    }

    // Epilogue: unpack, add bias, store
    const int grow = bm * BM + ty * 8;
    const int gcol = bn * BN + tx * 8;
    float bv[8];
#pragma unroll
    for (int j = 0; j < 8; j++) bv[j] = bias[gcol + j];

#pragma unroll
    for (int i = 0; i < 8; i++) {
        size_t off = (size_t)(grow + i) * O_SZ + gcol;
#pragma unroll
        for (int j = 0; j < 4; j++) {
            float lo, hi;
            asm("mov.b64 {%0, %1}, %2;" : "=f"(lo), "=f"(hi) : "l"(acc[i][j]));
            *(float2*)(C + off + j * 2) =
                make_float2(lo + bv[j * 2], hi + bv[j * 2 + 1]);
        }
    }
}

// ---------------------------------------------------------------------------
// Launch
// ---------------------------------------------------------------------------
extern "C" void kernel_launch(void* const* d_in, const int* in_sizes, int n_in,
                              void* d_out, int out_size) {
    const float* data = (const float*)d_in[0];
    const float* wr   = (const float*)d_in[1];
    const float* wi   = (const float*)d_in[2];
    const float* bias = (const float*)d_in[3];
    const int*   zmat = (const int*)d_in[4];
    float*       out  = (float*)d_out;

    kern_rowfft<<<O_SZ, 512>>>(wr, wi, zmat);
    kern_transpose<<<dim3(I_SZ / 32, O_SZ / 32), dim3(32, 8)>>>();
    kern_colfft<<<I_SZ, 512>>>();
    kern_gemm<<<dim3(O_SZ / BN, B_SZ / BM), 256>>>(data, bias, out);
}

// round 4
// speedup vs baseline: 1.7852x; 1.7852x over previous
#include <cuda_runtime.h>
#include <cuda_bf16.h>
#include <cstdint>

#define B_SZ 2048
#define O_SZ 4096
#define I_SZ 4096
#define N_FFT 4096
#define LOG_N 12
#define KEXP (3 * I_SZ)          // 12288: [hi | lo | hi] along K

// ---------------------------------------------------------------------------
// Scratch (device globals: no allocation allowed)
// ---------------------------------------------------------------------------
__device__ float2 g_Y [(size_t)O_SZ * I_SZ];
__device__ float2 g_Yt[(size_t)I_SZ * O_SZ];
__device__ float  g_Wt[(size_t)I_SZ * O_SZ];          // W^T: g_Wt[i][o] = W[o][i]
__device__ __nv_bfloat16 g_Ap[(size_t)B_SZ * KEXP];   // A' = [hi|lo|hi]
__device__ __nv_bfloat16 g_Bp[(size_t)O_SZ * KEXP];   // B' = [hi|hi|lo]

// ---------------------------------------------------------------------------
// Helpers
// ---------------------------------------------------------------------------
__device__ __forceinline__ uint32_t smem_u32(const void* p) {
    uint32_t a;
    asm("{ .reg .u64 t; cvta.to.shared.u64 t, %1; cvt.u32.u64 %0, t; }" : "=r"(a) : "l"(p));
    return a;
}
// SW128 swizzle restricted to 128B rows (kb < 128): xor term = (row&7)<<4
__device__ __forceinline__ uint32_t swz(int row, int kb) {
    return (uint32_t)(row * 128 + (kb ^ ((row & 7) << 4)));
}

#define CP16(dst, src) asm volatile("cp.async.cg.shared.global [%0], [%1], 16;" :: "r"(dst), "l"(src) : "memory")
#define CP_COMMIT()    asm volatile("cp.async.commit_group;" ::: "memory")

#define LDSM_X4(r0, r1, r2, r3, addr) \
    asm volatile("ldmatrix.sync.aligned.m8n8.x4.shared.b16 {%0,%1,%2,%3}, [%4];" \
        : "=r"(r0), "=r"(r1), "=r"(r2), "=r"(r3) : "r"(addr))

#define MMA16816(d, a, b) \
    asm volatile("mma.sync.aligned.m16n8k16.row.col.f32.bf16.bf16.f32 " \
        "{%0,%1,%2,%3}, {%4,%5,%6,%7}, {%8,%9}, {%0,%1,%2,%3};" \
        : "+f"((d)[0]), "+f"((d)[1]), "+f"((d)[2]), "+f"((d)[3]) \
        : "r"((a)[0]), "r"((a)[1]), "r"((a)[2]), "r"((a)[3]), "r"((b)[0]), "r"((b)[1]))

// ---------------------------------------------------------------------------
// FFT machinery (unchanged, verified in round 2)
// ---------------------------------------------------------------------------
__device__ __forceinline__ float2 cmul(float2 a, float2 b) {
    return make_float2(a.x * b.x - a.y * b.y, a.x * b.y + a.y * b.x);
}

__device__ __forceinline__ void ifft4096(float2* xs, const float2* tw) {
#pragma unroll
    for (int s = 1; s <= LOG_N; s++) {
        const int half = 1 << (s - 1);
        const int twsh = LOG_N - s;
        __syncthreads();
#pragma unroll
        for (int t = threadIdx.x; t < N_FFT / 2; t += 512) {
            int k  = t & (half - 1);
            int i0 = ((t >> (s - 1)) << s) + k;
            int i1 = i0 + half;
            int j  = k << twsh;
            float2 w;
            if (j < 1024) {
                w = tw[j];
            } else {
                float2 q = tw[j - 1024];
                w = make_float2(-q.y, q.x);
            }
            float2 u = xs[i0];
            float2 v = cmul(xs[i1], w);
            xs[i0] = make_float2(u.x + v.x, u.y + v.y);
            xs[i1] = make_float2(u.x - v.x, u.y - v.y);
        }
    }
    __syncthreads();
}

__device__ __forceinline__ void build_twiddles(float2* tw) {
    for (int j = threadIdx.x; j < 1024; j += 512) {
        float s, c;
        sincosf(1.5339807878856412e-3f * (float)j, &s, &c);
        tw[j] = make_float2(c, s);
    }
}

__global__ __launch_bounds__(512) void kern_rowfft(const float* __restrict__ wr,
                                                   const float* __restrict__ wi,
                                                   const int* __restrict__ zmat) {
    __shared__ float2 xs[N_FFT];
    __shared__ float2 tw[1024];
    const int p = blockIdx.x;
    build_twiddles(tw);

    const size_t base = (size_t)p * I_SZ;
    for (int k = threadIdx.x; k < N_FFT; k += 512) {
        float2 v = make_float2(0.f, 0.f);
        if (k <= I_SZ / 2) {
            int z = zmat[base + k];
            if (z <= 8388608) {
                float sc = (k == 0 || k == I_SZ / 2) ? 1.0f : 2.0f;
                v = make_float2(wr[base + k] * sc, wi[base + k] * sc);
            }
        }
        xs[__brev((unsigned)k) >> (32 - LOG_N)] = v;
    }
    ifft4096(xs, tw);

    float2* out = g_Y + base;
    for (int i = threadIdx.x; i < N_FFT; i += 512) out[i] = xs[i];
}

__global__ void kern_transpose() {
    __shared__ float2 tile[32][33];
    int x = blockIdx.x * 32 + threadIdx.x;
    int y = blockIdx.y * 32 + threadIdx.y;
#pragma unroll
    for (int j = 0; j < 32; j += 8)
        tile[threadIdx.y + j][threadIdx.x] = g_Y[(size_t)(y + j) * I_SZ + x];
    __syncthreads();
    int x2 = blockIdx.y * 32 + threadIdx.x;
    int y2 = blockIdx.x * 32 + threadIdx.y;
#pragma unroll
    for (int j = 0; j < 32; j += 8)
        g_Yt[(size_t)(y2 + j) * O_SZ + x2] = tile[threadIdx.x][threadIdx.y + j];
}

__global__ __launch_bounds__(512) void kern_colfft() {
    __shared__ float2 xs[N_FFT];
    __shared__ float2 tw[1024];
    const int i = blockIdx.x;
    build_twiddles(tw);

    const float2* row = g_Yt + (size_t)i * O_SZ;
    for (int p = threadIdx.x; p < N_FFT; p += 512)
        xs[__brev((unsigned)p) >> (32 - LOG_N)] = row[p];
    ifft4096(xs, tw);

    float* out = g_Wt + (size_t)i * O_SZ;
    const float scale = 1.0f / 16777216.0f;
    for (int o = threadIdx.x; o < N_FFT; o += 512) out[o] = xs[o].x * scale;
}

// ---------------------------------------------------------------------------
// Split-bf16 conversions (unchanged)
// ---------------------------------------------------------------------------
__global__ __launch_bounds__(256) void kern_convA(const float* __restrict__ data) {
    size_t idx = (size_t)blockIdx.x * 256 + threadIdx.x;
    float x = data[idx];
    __nv_bfloat16 hi = __float2bfloat16(x);
    __nv_bfloat16 lo = __float2bfloat16(x - __bfloat162float(hi));
    size_t b = idx >> 12, i = idx & 4095;
    __nv_bfloat16* row = g_Ap + b * KEXP;
    row[i]            = hi;
    row[I_SZ + i]     = lo;
    row[2 * I_SZ + i] = hi;
}

__global__ void kern_convB() {
    __shared__ float tile[32][33];
    int o0 = blockIdx.x * 32, i0 = blockIdx.y * 32;
    int tx = threadIdx.x, ty = threadIdx.y;
#pragma unroll
    for (int j = 0; j < 32; j += 8)
        tile[ty + j][tx] = g_Wt[(size_t)(i0 + ty + j) * O_SZ + o0 + tx];
    __syncthreads();
#pragma unroll
    for (int j = 0; j < 32; j += 8) {
        int o = o0 + ty + j;
        int i = i0 + tx;
        float x = tile[tx][ty + j];
        __nv_bfloat16 hi = __float2bfloat16(x);
        __nv_bfloat16 lo = __float2bfloat16(x - __bfloat162float(hi));
        __nv_bfloat16* row = g_Bp + (size_t)o * KEXP;
        row[i]            = hi;
        row[I_SZ + i]     = hi;
        row[2 * I_SZ + i] = lo;
    }
}

// ---------------------------------------------------------------------------
// mma.sync GEMM: C[b][o] = sum_k A'[b][k] * B'[o][k] + bias[o]
// CTA 128x128, BK=64 (128B rows, SW128), 3-stage cp.async pipeline,
// 8 warps (4Mx2N), warp tile 32x64, mma.m16n8k16 bf16 -> f32.
// ---------------------------------------------------------------------------
#define GM 128
#define GN 128
#define TILE_K 64
#define STAGES 3
#define A_ST (GM * 128)                 // 16KB
#define B_ST (GN * 128)                 // 16KB
#define STAGE_BYTES (A_ST + B_ST)       // 32KB
#define NT (KEXP / TILE_K)              // 192
#define GEMM_SMEM (STAGES * STAGE_BYTES)

__global__ __launch_bounds__(256) void kern_gemm_mma(const float* __restrict__ bias,
                                                     float* __restrict__ C) {
    extern __shared__ char dsm[];
    const uint32_t smem = smem_u32(dsm);
    const int tid  = threadIdx.x;
    const int wid  = tid >> 5;
    const int lane = tid & 31;
    const int wm   = wid & 3;            // warp M index (0..3)
    const int wn   = wid >> 2;           // warp N index (0..1)
    const int m0   = wm * 32;
    const int n0   = wn * 64;

    const __nv_bfloat16* gA = g_Ap + (size_t)(blockIdx.y * GM) * KEXP;
    const __nv_bfloat16* gB = g_Bp + (size_t)(blockIdx.x * GN) * KEXP;

    // per-thread cp.async source/dest geometry: 4 rows/warp-op, 8 x 16B per row
    const int crow = tid >> 3;           // 0..31
    const int ccol = tid & 7;            // 0..7

    auto load_tile = [&](int t, int s) {
        const uint32_t sA = smem + s * STAGE_BYTES;
        const uint32_t sB = sA + A_ST;
        const char* srcA = (const char*)(gA + (size_t)t * TILE_K);
        const char* srcB = (const char*)(gB + (size_t)t * TILE_K);
#pragma unroll
        for (int r = 0; r < 4; r++) {
            int row = crow + r * 32;
            CP16(sA + swz(row, ccol * 16), srcA + (size_t)row * (KEXP * 2) + ccol * 16);
        }
#pragma unroll
        for (int r = 0; r < 4; r++) {
            int row = crow + r * 32;
            CP16(sB + swz(row, ccol * 16), srcB + (size_t)row * (KEXP * 2) + ccol * 16);
        }
    };

    float acc[2][8][4];
#pragma unroll
    for (int mt = 0; mt < 2; mt++)
#pragma unroll
        for (int nt = 0; nt < 8; nt++)
#pragma unroll
            for (int j = 0; j < 4; j++) acc[mt][nt][j] = 0.f;

    // ldmatrix lane geometry (offsets within tile, swizzled)
    const int l7 = lane & 7;
    // A: lanes 0-7 -> (row+0, kb+0); 8-15 -> (+8, 0); 16-23 -> (0, +16); 24-31 -> (+8, +16)
    const int a_row = m0 + ((lane >> 3) & 1) * 8 + l7;
    const int a_kb  = ((lane >> 4) & 1) * 16;
    // B: lanes 0-7 -> (row+0, kb+0); 8-15 -> (0, +16); 16-23 -> (+8, 0); 24-31 -> (+8, +16)
    const int b_row = n0 + ((lane >> 4) & 1) * 8 + l7;
    const int b_kb  = ((lane >> 3) & 1) * 16;

    // prologue
    load_tile(0, 0); CP_COMMIT();
    load_tile(1, 1); CP_COMMIT();

    for (int t = 0; t < NT; t++) {
        asm volatile("cp.async.wait_group 1;" ::: "memory");
        __syncthreads();

        const int s = t % STAGES;
        const uint32_t sA = smem + s * STAGE_BYTES;
        const uint32_t sB = sA + A_ST;

#pragma unroll
        for (int ks = 0; ks < 4; ks++) {
            const int kb = ks * 32;
            uint32_t a[2][4], b[8][2];
#pragma unroll
            for (int mt = 0; mt < 2; mt++) {
                uint32_t addr = sA + swz(a_row + mt * 16, kb + a_kb);
                LDSM_X4(a[mt][0], a[mt][1], a[mt][2], a[mt][3], addr);
            }
#pragma unroll
            for (int bt = 0; bt < 4; bt++) {
                uint32_t addr = sB + swz(b_row + bt * 16, kb + b_kb);
                LDSM_X4(b[2 * bt][0], b[2 * bt][1], b[2 * bt + 1][0], b[2 * bt + 1][1], addr);
            }
#pragma unroll
            for (int mt = 0; mt < 2; mt++)
#pragma unroll
                for (int nt = 0; nt < 8; nt++)
                    MMA16816(acc[mt][nt], a[mt], b[nt]);
        }
        __syncthreads();

        const int tn = t + 2;
        if (tn < NT) load_tile(tn, tn % STAGES);
        CP_COMMIT();
    }

    // epilogue: bias + store
    const int gid = lane >> 2;          // 0..7
    const int tig = lane & 3;           // 0..3
#pragma unroll
    for (int mt = 0; mt < 2; mt++) {
        const int row0 = blockIdx.y * GM + m0 + mt * 16 + gid;
#pragma unroll
        for (int nt = 0; nt < 8; nt++) {
            const int col = blockIdx.x * GN + n0 + nt * 8 + 2 * tig;
            float b0 = __ldg(bias + col), b1 = __ldg(bias + col + 1);
            *(float2*)(C + (size_t)row0 * O_SZ + col) =
                make_float2(acc[mt][nt][0] + b0, acc[mt][nt][1] + b1);
            *(float2*)(C + (size_t)(row0 + 8) * O_SZ + col) =
                make_float2(acc[mt][nt][2] + b0, acc[mt][nt][3] + b1);
        }
    }
}

// ---------------------------------------------------------------------------
// Launch
// ---------------------------------------------------------------------------
extern "C" void kernel_launch(void* const* d_in, const int* in_sizes, int n_in,
                              void* d_out, int out_size) {
    const float* data = (const float*)d_in[0];
    const float* wr   = (const float*)d_in[1];
    const float* wi   = (const float*)d_in[2];
    const float* bias = (const float*)d_in[3];
    const int*   zmat = (const int*)d_in[4];
    float*       out  = (float*)d_out;

    cudaFuncSetAttribute(kern_gemm_mma, cudaFuncAttributeMaxDynamicSharedMemorySize, GEMM_SMEM);

    kern_convA<<<(B_SZ * I_SZ) / 256, 256>>>(data);
    kern_rowfft<<<O_SZ, 512>>>(wr, wi, zmat);
    kern_transpose<<<dim3(I_SZ / 32, O_SZ / 32), dim3(32, 8)>>>();
    kern_colfft<<<I_SZ, 512>>>();
    kern_convB<<<dim3(O_SZ / 32, I_SZ / 32), dim3(32, 8)>>>();
    kern_gemm_mma<<<dim3(O_SZ / GN, B_SZ / GM), 256, GEMM_SMEM>>>(bias, out);
}

// round 6
// speedup vs baseline: 2.6823x; 1.5025x over previous
#include <cuda_runtime.h>
#include <cuda_bf16.h>
#include <cstdint>

#define B_SZ 2048
#define O_SZ 4096
#define I_SZ 4096
#define KEXP (3 * I_SZ)          // 12288: A'=[hi|lo|hi], B'=[hi|hi|lo]
#define M_HALF 2048              // I/2
#define HSTR 2056                // padded row stride for H (float2 units)

// ---------------------------------------------------------------------------
// Scratch (device globals: no allocation allowed)
// ---------------------------------------------------------------------------
__device__ float2 g_T [(size_t)4096 * HSTR];          // T[k][p] then reused as H[p][k]
__device__ float2 g_U [(size_t)2049 * 4096];          // U[k][p] after axis-0 ifft
__device__ __nv_bfloat16 g_Ap[(size_t)B_SZ * KEXP];
__device__ __nv_bfloat16 g_Bp[(size_t)O_SZ * KEXP];

// ---------------------------------------------------------------------------
// Helpers
// ---------------------------------------------------------------------------
__device__ __forceinline__ uint32_t smem_u32(const void* p) {
    uint32_t a;
    asm("{ .reg .u64 t; cvta.to.shared.u64 t, %1; cvt.u32.u64 %0, t; }" : "=r"(a) : "l"(p));
    return a;
}
__device__ __forceinline__ uint32_t swz(int row, int kb) {
    return (uint32_t)(row * 128 + (kb ^ ((row & 7) << 4)));
}
#define CP16(dst, src) asm volatile("cp.async.cg.shared.global [%0], [%1], 16;" :: "r"(dst), "l"(src) : "memory")
#define CP_COMMIT()    asm volatile("cp.async.commit_group;" ::: "memory")
#define LDSM_X4(r0, r1, r2, r3, addr) \
    asm volatile("ldmatrix.sync.aligned.m8n8.x4.shared.b16 {%0,%1,%2,%3}, [%4];" \
        : "=r"(r0), "=r"(r1), "=r"(r2), "=r"(r3) : "r"(addr))
#define MMA16816(d, a, b) \
    asm volatile("mma.sync.aligned.m16n8k16.row.col.f32.bf16.bf16.f32 " \
        "{%0,%1,%2,%3}, {%4,%5,%6,%7}, {%8,%9}, {%0,%1,%2,%3};" \
        : "+f"((d)[0]), "+f"((d)[1]), "+f"((d)[2]), "+f"((d)[3]) \
        : "r"((a)[0]), "r"((a)[1]), "r"((a)[2]), "r"((a)[3]), "r"((b)[0]), "r"((b)[1]))

__device__ __forceinline__ float2 cmul(float2 a, float2 b) {
    return make_float2(a.x * b.x - a.y * b.y, a.x * b.y + a.y * b.x);
}
__device__ __forceinline__ float2 cadd(float2 a, float2 b) { return make_float2(a.x + b.x, a.y + b.y); }
__device__ __forceinline__ float2 csub(float2 a, float2 b) { return make_float2(a.x - b.x, a.y - b.y); }
__device__ __forceinline__ float2 rot90(float2 a) { return make_float2(-a.y, a.x); }  // * i

// tw[j] = e^{+2*pi*i*j/4096}, j in [0,1024). twid handles j in [0,2048).
__device__ __forceinline__ float2 twid(const float2* tw, int j) {
    float2 t = tw[j & 1023];
    return (j & 1024) ? rot90(t) : t;
}
__device__ __forceinline__ void build_twiddles(float2* tw) {
    for (int j = threadIdx.x; j < 1024; j += 512) {
        float s, c;
        sincosf(1.5339807878856412e-3f * (float)j, &s, &c);   // 2*pi/4096 * j
        tw[j] = make_float2(c, s);
    }
}

// ---------------------------------------------------------------------------
// In-smem IFFT (sign +), bit-reversed input, natural output, unnormalized.
// Radix-2 stage pairs fused into radix-4 passes. 512 threads.
// Twiddle for stage s: e^{2*pi*i*k/2^s} = tw4096 index k<<(12-s)  (LOGN-indep).
// ---------------------------------------------------------------------------
template <int LOGN>
__device__ __forceinline__ void ifft_smem(float2* xs, const float2* tw) {
    constexpr int N = 1 << LOGN;
    int s = 1;
    if (LOGN & 1) {                       // one plain radix-2 stage (w = 1)
        __syncthreads();
        for (int t = threadIdx.x; t < N / 2; t += 512) {
            int i0 = 2 * t;
            float2 u = xs[i0], v = xs[i0 + 1];
            xs[i0] = cadd(u, v);
            xs[i0 + 1] = csub(u, v);
        }
        s = 2;
    }
#pragma unroll
    for (; s <= LOGN; s += 2) {           // fused stages s, s+1
        const int h = 1 << (s - 1);
        __syncthreads();
        for (int u = threadIdx.x; u < N / 4; u += 512) {
            int k  = u & (h - 1);
            int i0 = ((u >> (s - 1)) << (s + 1)) + k;
            float2 a = xs[i0], b = xs[i0 + h], c = xs[i0 + 2 * h], d = xs[i0 + 3 * h];
            float2 w1 = twid(tw, k << (12 - s));
            b = cmul(b, w1);
            d = cmul(d, w1);
            float2 t0 = cadd(a, b), t1 = csub(a, b);
            float2 t2 = cadd(c, d), t3 = csub(c, d);
            float2 w2 = twid(tw, k << (11 - s));
            t2 = cmul(t2, w2);
            t3 = rot90(cmul(t3, w2));     // * i*w2
            xs[i0]         = cadd(t0, t2);
            xs[i0 + 2 * h] = csub(t0, t2);
            xs[i0 + h]     = cadd(t1, t3);
            xs[i0 + 3 * h] = csub(t1, t3);
        }
    }
    __syncthreads();
}

// ---------------------------------------------------------------------------
// K1: masked transpose  T[k][p] = mask*(wr[p][k] + i*wi[p][k]),  k<=2048
// NO doubling: the half-spectrum irfft packing supplies the Hermitian mirror.
// ---------------------------------------------------------------------------
__global__ void kern_mtrans(const float* __restrict__ wr, const float* __restrict__ wi,
                            const int* __restrict__ zmat) {
    __shared__ float2 tile[32][33];
    const int k0 = blockIdx.y * 32, p0 = blockIdx.x * 32;
    const int tx = threadIdx.x, ty = threadIdx.y;
#pragma unroll
    for (int j = 0; j < 32; j += 8) {
        int p = p0 + ty + j, k = k0 + tx;
        float2 v = make_float2(0.f, 0.f);
        if (k <= M_HALF) {
            size_t idx = (size_t)p * I_SZ + k;
            if (zmat[idx] <= 8388608)
                v = make_float2(wr[idx], wi[idx]);
        }
        tile[ty + j][tx] = v;
    }
    __syncthreads();
#pragma unroll
    for (int j = 0; j < 32; j += 8) {
        int k = k0 + ty + j;
        if (k <= M_HALF)
            g_T[(size_t)k * 4096 + p0 + tx] = tile[tx][ty + j];
    }
}

// ---------------------------------------------------------------------------
// K2: axis-0 IFFT (length 4096) on each of the 2049 columns (stored as rows).
// ---------------------------------------------------------------------------
__global__ __launch_bounds__(512) void kern_fft0() {
    __shared__ float2 xs[4096];
    __shared__ float2 tw[1024];
    const int k = blockIdx.x;                 // 0..2048
    build_twiddles(tw);
    const float2* row = g_T + (size_t)k * 4096;
    for (int p = threadIdx.x; p < 4096; p += 512)
        xs[__brev((unsigned)p) >> 20] = row[p];
    ifft_smem<12>(xs, tw);
    float2* out = g_U + (size_t)k * 4096;
    for (int p = threadIdx.x; p < 4096; p += 512) out[p] = xs[p];
}

// ---------------------------------------------------------------------------
// K3: transpose back  H[p][k] = U[k][p]  (H rows padded to HSTR)
// ---------------------------------------------------------------------------
__global__ void kern_trback() {
    __shared__ float2 tile[32][33];
    const int p0 = blockIdx.x * 32, k0 = blockIdx.y * 32;
    const int tx = threadIdx.x, ty = threadIdx.y;
#pragma unroll
    for (int j = 0; j < 32; j += 8) {
        int k = k0 + ty + j;
        tile[ty + j][tx] = (k <= M_HALF) ? g_U[(size_t)k * 4096 + p0 + tx]
                                         : make_float2(0.f, 0.f);
    }
    __syncthreads();
#pragma unroll
    for (int j = 0; j < 32; j += 8) {
        int k = k0 + tx;
        if (k <= M_HALF)
            g_T[(size_t)(p0 + ty + j) * HSTR + k] = tile[tx][ty + j];
    }
}

// ---------------------------------------------------------------------------
// K4: per row o: real IFFT of half-spectrum H[o][0..2048] via 2048-pt complex
// IFFT + pack; split to bf16 hi/lo and write g_Bp[o] = [hi|hi|lo] directly.
// Z[k] = ((H+C) + i*w_k*(H-C))/2, C=conj(H[M-k]); x[2m]=Re z, x[2m+1]=Im z.
// ---------------------------------------------------------------------------
__global__ __launch_bounds__(512) void kern_irfft() {
    __shared__ float2 hbuf[2049];
    __shared__ float2 xs[2048];
    __shared__ float2 tw[1024];
    const int o = blockIdx.x;
    build_twiddles(tw);

    const float2* hrow = g_T + (size_t)o * HSTR;
    for (int k = threadIdx.x; k < 2049; k += 512) hbuf[k] = hrow[k];
    __syncthreads();

    for (int k = threadIdx.x; k < 2048; k += 512) {
        float2 Hk, Ck;
        if (k == 0) {
            Hk = make_float2(hbuf[0].x, 0.f);
            Ck = make_float2(hbuf[M_HALF].x, 0.f);
        } else {
            Hk = hbuf[k];
            float2 c = hbuf[M_HALF - k];
            Ck = make_float2(c.x, -c.y);
        }
        float2 S = cadd(Hk, Ck);
        float2 D = csub(Hk, Ck);
        float2 G = cadd(S, rot90(cmul(D, twid(tw, k))));   // S + i*w_k*D  (= 2*Z[k])
        xs[__brev((unsigned)k) >> 21] = G;
    }
    ifft_smem<11>(xs, tw);

    const float s = 1.0f / 16777216.0f;   // 1/(O * 2M) = 1/(4096*4096)
    __nv_bfloat16* rowB = g_Bp + (size_t)o * KEXP;
    for (int m = threadIdx.x; m < 2048; m += 512) {
        float x0 = xs[m].x * s;
        float x1 = xs[m].y * s;
        __nv_bfloat16 h0 = __float2bfloat16(x0);
        __nv_bfloat16 h1 = __float2bfloat16(x1);
        __nv_bfloat16 l0 = __float2bfloat16(x0 - __bfloat162float(h0));
        __nv_bfloat16 l1 = __float2bfloat16(x1 - __bfloat162float(h1));
        __nv_bfloat162 hp; hp.x = h0; hp.y = h1;
        __nv_bfloat162 lp; lp.x = l0; lp.y = l1;
        *(__nv_bfloat162*)(rowB + 2 * m)            = hp;
        *(__nv_bfloat162*)(rowB + I_SZ + 2 * m)     = hp;
        *(__nv_bfloat162*)(rowB + 2 * I_SZ + 2 * m) = lp;
    }
}

// ---------------------------------------------------------------------------
// convA: data -> A' = [hi | lo | hi]
// ---------------------------------------------------------------------------
__global__ __launch_bounds__(256) void kern_convA(const float* __restrict__ data) {
    size_t idx = (size_t)blockIdx.x * 256 + threadIdx.x;
    float x = data[idx];
    __nv_bfloat16 hi = __float2bfloat16(x);
    __nv_bfloat16 lo = __float2bfloat16(x - __bfloat162float(hi));
    size_t b = idx >> 12, i = idx & 4095;
    __nv_bfloat16* row = g_Ap + b * KEXP;
    row[i]            = hi;
    row[I_SZ + i]     = lo;
    row[2 * I_SZ + i] = hi;
}

// ---------------------------------------------------------------------------
// mma.sync GEMM (unchanged from round 4, passing): CTA 128x128, BK=64,
// 3-stage cp.async, 8 warps (4Mx2N), warp tile 32x64, m16n8k16 bf16->f32.
// ---------------------------------------------------------------------------
#define GM 128
#define GN 128
#define TILE_K 64
#define STAGES 3
#define A_ST (GM * 128)
#define B_ST (GN * 128)
#define STAGE_BYTES (A_ST + B_ST)
#define NT (KEXP / TILE_K)
#define GEMM_SMEM (STAGES * STAGE_BYTES)

__global__ __launch_bounds__(256) void kern_gemm_mma(const float* __restrict__ bias,
                                                     float* __restrict__ C) {
    extern __shared__ char dsm[];
    const uint32_t smem = smem_u32(dsm);
    const int tid  = threadIdx.x;
    const int wid  = tid >> 5;
    const int lane = tid & 31;
    const int m0   = (wid & 3) * 32;
    const int n0   = (wid >> 2) * 64;

    const __nv_bfloat16* gA = g_Ap + (size_t)(blockIdx.y * GM) * KEXP;
    const __nv_bfloat16* gB = g_Bp + (size_t)(blockIdx.x * GN) * KEXP;

    const int crow = tid >> 3;
    const int ccol = tid & 7;

    auto load_tile = [&](int t, int s) {
        const uint32_t sA = smem + s * STAGE_BYTES;
        const uint32_t sB = sA + A_ST;
        const char* srcA = (const char*)(gA + (size_t)t * TILE_K);
        const char* srcB = (const char*)(gB + (size_t)t * TILE_K);
#pragma unroll
        for (int r = 0; r < 4; r++) {
            int row = crow + r * 32;
            CP16(sA + swz(row, ccol * 16), srcA + (size_t)row * (KEXP * 2) + ccol * 16);
        }
#pragma unroll
        for (int r = 0; r < 4; r++) {
            int row = crow + r * 32;
            CP16(sB + swz(row, ccol * 16), srcB + (size_t)row * (KEXP * 2) + ccol * 16);
        }
    };

    float acc[2][8][4];
#pragma unroll
    for (int mt = 0; mt < 2; mt++)
#pragma unroll
        for (int nt = 0; nt < 8; nt++)
#pragma unroll
            for (int j = 0; j < 4; j++) acc[mt][nt][j] = 0.f;

    const int l7 = lane & 7;
    const int a_row = m0 + ((lane >> 3) & 1) * 8 + l7;
    const int a_kb  = ((lane >> 4) & 1) * 16;
    const int b_row = n0 + ((lane >> 4) & 1) * 8 + l7;
    const int b_kb  = ((lane >> 3) & 1) * 16;

    load_tile(0, 0); CP_COMMIT();
    load_tile(1, 1); CP_COMMIT();

    for (int t = 0; t < NT; t++) {
        asm volatile("cp.async.wait_group 1;" ::: "memory");
        __syncthreads();

        const int s = t % STAGES;
        const uint32_t sA = smem + s * STAGE_BYTES;
        const uint32_t sB = sA + A_ST;

#pragma unroll
        for (int ks = 0; ks < 4; ks++) {
            const int kb = ks * 32;
            uint32_t a[2][4], b[8][2];
#pragma unroll
            for (int mt = 0; mt < 2; mt++) {
                uint32_t addr = sA + swz(a_row + mt * 16, kb + a_kb);
                LDSM_X4(a[mt][0], a[mt][1], a[mt][2], a[mt][3], addr);
            }
#pragma unroll
            for (int bt = 0; bt < 4; bt++) {
                uint32_t addr = sB + swz(b_row + bt * 16, kb + b_kb);
                LDSM_X4(b[2 * bt][0], b[2 * bt][1], b[2 * bt + 1][0], b[2 * bt + 1][1], addr);
            }
#pragma unroll
            for (int mt = 0; mt < 2; mt++)
#pragma unroll
                for (int nt = 0; nt < 8; nt++)
                    MMA16816(acc[mt][nt], a[mt], b[nt]);
        }
        __syncthreads();

        const int tn = t + 2;
        if (tn < NT) load_tile(tn, tn % STAGES);
        CP_COMMIT();
    }

    const int gid = lane >> 2;
    const int tig = lane & 3;
#pragma unroll
    for (int mt = 0; mt < 2; mt++) {
        const int row0 = blockIdx.y * GM + m0 + mt * 16 + gid;
#pragma unroll
        for (int nt = 0; nt < 8; nt++) {
            const int col = blockIdx.x * GN + n0 + nt * 8 + 2 * tig;
            float b0 = __ldg(bias + col), b1 = __ldg(bias + col + 1);
            *(float2*)(C + (size_t)row0 * O_SZ + col) =
                make_float2(acc[mt][nt][0] + b0, acc[mt][nt][1] + b1);
            *(float2*)(C + (size_t)(row0 + 8) * O_SZ + col) =
                make_float2(acc[mt][nt][2] + b0, acc[mt][nt][3] + b1);
        }
    }
}

// ---------------------------------------------------------------------------
// Launch
// ---------------------------------------------------------------------------
extern "C" void kernel_launch(void* const* d_in, const int* in_sizes, int n_in,
                              void* d_out, int out_size) {
    const float* data = (const float*)d_in[0];
    const float* wr   = (const float*)d_in[1];
    const float* wi   = (const float*)d_in[2];
    const float* bias = (const float*)d_in[3];
    const int*   zmat = (const int*)d_in[4];
    float*       out  = (float*)d_out;

    cudaFuncSetAttribute(kern_gemm_mma, cudaFuncAttributeMaxDynamicSharedMemorySize, GEMM_SMEM);

    kern_convA<<<(B_SZ * I_SZ) / 256, 256>>>(data);
    kern_mtrans<<<dim3(4096 / 32, 65), dim3(32, 8)>>>(wr, wi, zmat);
    kern_fft0<<<2049, 512>>>();
    kern_trback<<<dim3(4096 / 32, 65), dim3(32, 8)>>>();
    kern_irfft<<<O_SZ, 512>>>();
    kern_gemm_mma<<<dim3(O_SZ / GN, B_SZ / GM), 256, GEMM_SMEM>>>(bias, out);
}